// round 5
// baseline (speedup 1.0000x reference)
#include <cuda_runtime.h>
#include <cuda_bf16.h>
#include <cstdint>

#define NN 100000
#define NE 800000
#define HD 128
#define ED 32
#define KZ 288   // Z row: [s(128) | deg*x(128) | sum_ea(32)]

// ---------------- device scratch (static, no allocations) ----------------
__device__ int   g_is64;                 // 1 if edge_index buffer is int64
__device__ int   g_deg[NN];
__device__ int   g_rowptr[NN + 1];
__device__ int   g_cursor[NN];
__device__ int   g_col[NE];
__device__ int   g_eid[NE];
__device__ float g_degf[NN];
__device__ __align__(16) float g_Z[(size_t)NN * KZ];   // 115.2 MB
__device__ __align__(16) float g_X1[(size_t)NN * HD];  // ping
__device__ __align__(16) float g_X2[(size_t)NN * HD];  // pong

// decode edge endpoint from the raw buffer, honoring detected dtype
__device__ __forceinline__ int edge_val(const void* ei, int idx) {
    if (g_is64) return (int)((const long long*)ei)[idx];
    return ((const int*)ei)[idx];
}

// ---------------- dtype detect ----------------
// int64 little-endian values < 2^31 => odd int32 words all zero.
// Genuine int32 node ids (< 100000) are ~never all-zero at 64 sampled odd slots.
__global__ void k_detect(const int* __restrict__ p) {
    int odd_nonzero = 0;
    for (int i = 1; i < 128; i += 2)
        if (p[i] != 0) odd_nonzero++;
    g_is64 = (odd_nonzero == 0) ? 1 : 0;
}

// ---------------- CSR build ----------------
__global__ void k_zero_deg() {
    int i = blockIdx.x * blockDim.x + threadIdx.x;
    if (i < NN) g_deg[i] = 0;
}

__global__ void k_hist(const void* __restrict__ ei) {
    int e = blockIdx.x * blockDim.x + threadIdx.x;
    if (e < NE) {
        int dst = edge_val(ei, NE + e);
        if ((unsigned)dst < NN) atomicAdd(&g_deg[dst], 1);
    }
}

// single-block scan: exclusive rowptr, cursor[i] = rowptr[i]
__global__ void k_scan() {
    __shared__ int sh[1024];
    __shared__ int carry;
    int tid = threadIdx.x;
    if (tid == 0) { carry = 0; g_rowptr[0] = 0; }
    __syncthreads();
    for (int base = 0; base < NN; base += 1024) {
        int i = base + tid;
        int v = (i < NN) ? g_deg[i] : 0;
        sh[tid] = v;
        __syncthreads();
        #pragma unroll
        for (int off = 1; off < 1024; off <<= 1) {
            int t = (tid >= off) ? sh[tid - off] : 0;
            __syncthreads();
            sh[tid] += t;
            __syncthreads();
        }
        int incl = sh[tid];
        int c = carry;
        if (i < NN) {
            g_rowptr[i + 1] = c + incl;
            g_cursor[i] = c + incl - v;
        }
        __syncthreads();
        if (tid == 1023) carry = c + sh[1023];
        __syncthreads();
    }
}

__global__ void k_fill(const void* __restrict__ ei) {
    int e = blockIdx.x * blockDim.x + threadIdx.x;
    if (e < NE) {
        int src = edge_val(ei, e);
        int dst = edge_val(ei, NE + e);
        if ((unsigned)src >= NN || (unsigned)dst >= NN) return;
        int p = atomicAdd(&g_cursor[dst], 1);
        g_col[p] = src;
        g_eid[p] = e;
    }
}

// per-node: sort row by eid (deterministic fp32 order), degf,
// Z[:,256:288] = sum edge_attr over in-edges (layer-invariant)
__global__ void k_pre(const float* __restrict__ ea) {
    int gid  = blockIdx.x * blockDim.x + threadIdx.x;
    int node = gid >> 5;
    int lane = gid & 31;
    if (node >= NN) return;
    int s = g_rowptr[node], e = g_rowptr[node + 1];
    if (lane == 0) {
        for (int i = s + 1; i < e; i++) {
            int ke = g_eid[i], kc = g_col[i];
            int j = i - 1;
            while (j >= s && g_eid[j] > ke) {
                g_eid[j + 1] = g_eid[j];
                g_col[j + 1] = g_col[j];
                j--;
            }
            g_eid[j + 1] = ke;
            g_col[j + 1] = kc;
        }
        g_degf[node] = (float)(e - s);
    }
    __syncwarp();
    float acc = 0.f;
    for (int p = s; p < e; p++)
        acc += ea[(size_t)g_eid[p] * ED + lane];
    g_Z[(size_t)node * KZ + 256 + lane] = acc;
}

// ---------------- per-layer SpMM: Z[:,0:128]=sum x[src], Z[:,128:256]=deg*x --
// sel: 0 -> external x, 1 -> g_X1, 2 -> g_X2
__global__ void k_spmm(const float* __restrict__ xext, int sel) {
    int gid  = blockIdx.x * blockDim.x + threadIdx.x;
    int node = gid >> 5;
    int lane = gid & 31;
    if (node >= NN) return;
    const float* xin = (sel == 0) ? xext : (sel == 1 ? g_X1 : g_X2);
    const float4* __restrict__ X4 = (const float4*)xin;
    int s = g_rowptr[node], e = g_rowptr[node + 1];
    float4 acc = make_float4(0.f, 0.f, 0.f, 0.f);
    for (int p = s; p < e; p++) {
        int c = g_col[p];
        float4 v = X4[(size_t)c * 32 + lane];
        acc.x += v.x; acc.y += v.y; acc.z += v.z; acc.w += v.w;
    }
    float4* Z4 = (float4*)g_Z;
    Z4[(size_t)node * 72 + lane] = acc;
    float dg = g_degf[node];
    float4 xv = X4[(size_t)node * 32 + lane];
    Z4[(size_t)node * 72 + 32 + lane] =
        make_float4(dg * xv.x, dg * xv.y, dg * xv.z, dg * xv.w);
}

// ---------------- per-layer GEMM: Y = leaky(Z @ W^T + deg*b) ----------------
// M=100000, N=128, K=288. BM=BN=128, BK=16, 256 threads, 8x8 microtile.
// osel: 1 -> g_X1, 2 -> g_X2, 3 -> external out
__global__ __launch_bounds__(256) void k_gemm(
    const float* __restrict__ W,     // [128][288]
    const float* __restrict__ bvec,  // [128]
    float* __restrict__ oext,
    int osel, int last)
{
    __shared__ float As[16][128];
    __shared__ float Bs[16][128];
    int t  = threadIdx.x;
    int tx = t & 15, ty = t >> 4;
    int m0 = blockIdx.x * 128;
    float* out = (osel == 3) ? oext : (osel == 1 ? g_X1 : g_X2);

    float acc[8][8];
    #pragma unroll
    for (int i = 0; i < 8; i++)
        #pragma unroll
        for (int j = 0; j < 8; j++) acc[i][j] = 0.f;

    for (int k0 = 0; k0 < KZ; k0 += 16) {
        #pragma unroll
        for (int h = 0; h < 2; h++) {
            int fid = t + h * 256;     // 0..511
            int row = fid >> 2;        // 0..127
            int c4  = fid & 3;
            int m = m0 + row;
            float4 v = make_float4(0.f, 0.f, 0.f, 0.f);
            if (m < NN)
                v = *(const float4*)&g_Z[(size_t)m * KZ + k0 + c4 * 4];
            As[c4 * 4 + 0][row] = v.x;
            As[c4 * 4 + 1][row] = v.y;
            As[c4 * 4 + 2][row] = v.z;
            As[c4 * 4 + 3][row] = v.w;
            float4 w = *(const float4*)&W[(size_t)row * KZ + k0 + c4 * 4];
            Bs[c4 * 4 + 0][row] = w.x;
            Bs[c4 * 4 + 1][row] = w.y;
            Bs[c4 * 4 + 2][row] = w.z;
            Bs[c4 * 4 + 3][row] = w.w;
        }
        __syncthreads();
        #pragma unroll
        for (int k = 0; k < 16; k++) {
            float a[8], b[8];
            *(float4*)&a[0] = *(const float4*)&As[k][ty * 8];
            *(float4*)&a[4] = *(const float4*)&As[k][ty * 8 + 4];
            *(float4*)&b[0] = *(const float4*)&Bs[k][tx * 8];
            *(float4*)&b[4] = *(const float4*)&Bs[k][tx * 8 + 4];
            #pragma unroll
            for (int i = 0; i < 8; i++)
                #pragma unroll
                for (int j = 0; j < 8; j++)
                    acc[i][j] += a[i] * b[j];
        }
        __syncthreads();
    }

    #pragma unroll
    for (int i = 0; i < 8; i++) {
        int m = m0 + ty * 8 + i;
        if (m >= NN) continue;
        float dg = g_degf[m];
        float vals[8];
        #pragma unroll
        for (int j = 0; j < 8; j++) {
            int n = tx * 8 + j;
            float y = acc[i][j] + dg * bvec[n];
            y = y > 0.f ? y : 0.01f * y;
            if (last) y = y > 0.f ? y : 0.01f * y;
            vals[j] = y;
        }
        float4* o4 = (float4*)&out[(size_t)m * HD + tx * 8];
        o4[0] = *(float4*)&vals[0];
        o4[1] = *(float4*)&vals[4];
    }
}

// ---------------- launch ----------------
extern "C" void kernel_launch(void* const* d_in, const int* in_sizes, int n_in,
                              void* d_out, int out_size) {
    // Resolve inputs by element count (ordering-proof; all counts distinct):
    //   x=12800000 f32, edge_index=1600000 (i32 or i64), edge_attr=25600000 f32,
    //   Wm=110592 f32, bm=384 f32
    const float* x  = nullptr;
    const void*  ei = nullptr;
    const float* ea = nullptr;
    const float* Wm = nullptr;
    const float* bm = nullptr;
    for (int i = 0; i < n_in; i++) {
        switch (in_sizes[i]) {
            case 12800000: x  = (const float*)d_in[i]; break;
            case 1600000:  ei = d_in[i];               break;
            case 25600000: ea = (const float*)d_in[i]; break;
            case 110592:   Wm = (const float*)d_in[i]; break;
            case 384:      bm = (const float*)d_in[i]; break;
            default: break;
        }
    }
    float* out = (float*)d_out;

    k_detect<<<1, 1>>>((const int*)ei);
    k_zero_deg<<<(NN + 255) / 256, 256>>>();
    k_hist<<<(NE + 255) / 256, 256>>>(ei);
    k_scan<<<1, 1024>>>();
    k_fill<<<(NE + 255) / 256, 256>>>(ei);
    k_pre<<<(NN * 32 + 255) / 256, 256>>>(ea);

    const int gemm_blocks = (NN + 127) / 128;
    // layer 0: in = external x, out = g_X1
    k_spmm<<<(NN * 32 + 255) / 256, 256>>>(x, 0);
    k_gemm<<<gemm_blocks, 256>>>(Wm + 0 * (size_t)HD * KZ, bm + 0 * HD, out, 1, 0);
    // layer 1: in = g_X1, out = g_X2
    k_spmm<<<(NN * 32 + 255) / 256, 256>>>(nullptr, 1);
    k_gemm<<<gemm_blocks, 256>>>(Wm + 1 * (size_t)HD * KZ, bm + 1 * HD, out, 2, 0);
    // layer 2: in = g_X2, out = external out (double leaky: activate_last)
    k_spmm<<<(NN * 32 + 255) / 256, 256>>>(nullptr, 2);
    k_gemm<<<gemm_blocks, 256>>>(Wm + 2 * (size_t)HD * KZ, bm + 2 * HD, out, 3, 1);
}

// round 6
// speedup vs baseline: 1.8197x; 1.8197x over previous
#include <cuda_runtime.h>
#include <cuda_bf16.h>
#include <cstdint>

#define NN 100000
#define NE 800000
#define HD 128
#define ED 32
#define KZ 288   // Z row: [s(128) | deg*x(128) | sum_ea(32)]
#define SK 40    // smem row stride in halfs (conflict-free for ldmatrix)

// ---------------- device scratch (static, no allocations) ----------------
__device__ int   g_is64;
__device__ int   g_deg[NN];
__device__ int   g_rowptr[NN + 1];
__device__ int   g_cursor[NN];
__device__ int   g_bsum[128];
__device__ int   g_col[NE];
__device__ int   g_eid[NE];
__device__ float g_degf[NN];
__device__ __align__(16) __nv_bfloat16 g_Zh[(size_t)NN * KZ];  // 57.6 MB
__device__ __align__(16) __nv_bfloat16 g_Zl[(size_t)NN * KZ];  // 57.6 MB
__device__ __align__(16) float g_X1[(size_t)NN * HD];
__device__ __align__(16) float g_X2[(size_t)NN * HD];

// ---------------- helpers ----------------
__device__ __forceinline__ int edge_val(const void* ei, int idx) {
    if (g_is64) return (int)((const long long*)ei)[idx];
    return ((const int*)ei)[idx];
}

__device__ __forceinline__ void split2(float v, __nv_bfloat16& h, __nv_bfloat16& l) {
    h = __float2bfloat16(v);
    l = __float2bfloat16(v - __bfloat162float(h));
}

__device__ __forceinline__ uint32_t pk(__nv_bfloat16 a, __nv_bfloat16 b) {
    __nv_bfloat162 t(a, b);   // a = low half (lower col index)
    return *reinterpret_cast<uint32_t*>(&t);
}

__device__ __forceinline__ void ldsm4(uint32_t* r, const void* p) {
    uint32_t a = (uint32_t)__cvta_generic_to_shared(p);
    asm volatile("ldmatrix.sync.aligned.m8n8.x4.shared.b16 {%0,%1,%2,%3}, [%4];\n"
        : "=r"(r[0]), "=r"(r[1]), "=r"(r[2]), "=r"(r[3]) : "r"(a));
}

__device__ __forceinline__ void mma16816(float* d, const uint32_t* a, const uint32_t* b) {
    asm volatile(
        "mma.sync.aligned.m16n8k16.row.col.f32.bf16.bf16.f32 "
        "{%0,%1,%2,%3}, {%4,%5,%6,%7}, {%8,%9}, {%0,%1,%2,%3};\n"
        : "+f"(d[0]), "+f"(d[1]), "+f"(d[2]), "+f"(d[3])
        : "r"(a[0]), "r"(a[1]), "r"(a[2]), "r"(a[3]), "r"(b[0]), "r"(b[1]));
}

// ---------------- dtype detect ----------------
__global__ void k_detect(const int* __restrict__ p) {
    int odd_nonzero = 0;
    for (int i = 1; i < 128; i += 2)
        if (p[i] != 0) odd_nonzero++;
    g_is64 = (odd_nonzero == 0) ? 1 : 0;
}

// ---------------- CSR build ----------------
__global__ void k_zero_deg() {
    int i = blockIdx.x * blockDim.x + threadIdx.x;
    if (i < NN) g_deg[i] = 0;
}

__global__ void k_hist(const void* __restrict__ ei) {
    int e = blockIdx.x * blockDim.x + threadIdx.x;
    if (e < NE) {
        int dst = edge_val(ei, NE + e);
        if ((unsigned)dst < NN) atomicAdd(&g_deg[dst], 1);
    }
}

// parallel scan, stage 1: per-block (1024) inclusive scan + block total
__global__ void k_scan1() {
    __shared__ int sh[1024];
    int tid = threadIdx.x;
    int i = blockIdx.x * 1024 + tid;
    int v = (i < NN) ? g_deg[i] : 0;
    sh[tid] = v;
    __syncthreads();
    #pragma unroll
    for (int off = 1; off < 1024; off <<= 1) {
        int t = (tid >= off) ? sh[tid - off] : 0;
        __syncthreads();
        sh[tid] += t;
        __syncthreads();
    }
    if (i < NN) g_rowptr[i + 1] = sh[tid];          // block-local inclusive
    if (tid == 1023) g_bsum[blockIdx.x] = sh[1023]; // block total
}

// stage 2: exclusive scan of 98 block totals (trivial)
__global__ void k_scan2(int nblk) {
    int acc = 0;
    for (int b = 0; b < nblk; b++) {
        int t = g_bsum[b];
        g_bsum[b] = acc;
        acc += t;
    }
}

// stage 3: apply offsets, produce rowptr + cursor
__global__ void k_scan3() {
    int i = blockIdx.x * blockDim.x + threadIdx.x;
    if (i < NN) {
        int incl = g_rowptr[i + 1] + g_bsum[i >> 10];
        g_rowptr[i + 1] = incl;
        g_cursor[i] = incl - g_deg[i];
    }
    if (i == 0) g_rowptr[0] = 0;
}

__global__ void k_fill(const void* __restrict__ ei) {
    int e = blockIdx.x * blockDim.x + threadIdx.x;
    if (e < NE) {
        int src = edge_val(ei, e);
        int dst = edge_val(ei, NE + e);
        if ((unsigned)src >= NN || (unsigned)dst >= NN) return;
        int p = atomicAdd(&g_cursor[dst], 1);
        g_col[p] = src;
        g_eid[p] = e;
    }
}

// per-node: sort row by eid (deterministic), degf, Zh/Zl[:,256:288] = sum edge_attr
__global__ void k_pre(const float* __restrict__ ea) {
    int gid  = blockIdx.x * blockDim.x + threadIdx.x;
    int node = gid >> 5;
    int lane = gid & 31;
    if (node >= NN) return;
    int s = g_rowptr[node], e = g_rowptr[node + 1];
    if (lane == 0) {
        for (int i = s + 1; i < e; i++) {
            int ke = g_eid[i], kc = g_col[i];
            int j = i - 1;
            while (j >= s && g_eid[j] > ke) {
                g_eid[j + 1] = g_eid[j];
                g_col[j + 1] = g_col[j];
                j--;
            }
            g_eid[j + 1] = ke;
            g_col[j + 1] = kc;
        }
        g_degf[node] = (float)(e - s);
    }
    __syncwarp();
    float acc = 0.f;
    for (int p = s; p < e; p++)
        acc += ea[(size_t)g_eid[p] * ED + lane];
    __nv_bfloat16 h, l;
    split2(acc, h, l);
    g_Zh[(size_t)node * KZ + 256 + lane] = h;
    g_Zl[(size_t)node * KZ + 256 + lane] = l;
}

// ---------------- per-layer SpMM -> split-bf16 Z ----------------
// sel: 0 -> external x, 1 -> g_X1, 2 -> g_X2
__global__ void k_spmm(const float* __restrict__ xext, int sel) {
    int gid  = blockIdx.x * blockDim.x + threadIdx.x;
    int node = gid >> 5;
    int lane = gid & 31;
    if (node >= NN) return;
    const float* xin = (sel == 0) ? xext : (sel == 1 ? g_X1 : g_X2);
    const float4* __restrict__ X4 = (const float4*)xin;
    int s = g_rowptr[node], e = g_rowptr[node + 1];
    float4 acc = make_float4(0.f, 0.f, 0.f, 0.f);
    for (int p = s; p < e; p++) {
        int c = g_col[p];
        float4 v = X4[(size_t)c * 32 + lane];
        acc.x += v.x; acc.y += v.y; acc.z += v.z; acc.w += v.w;
    }
    __nv_bfloat16 h0, h1, h2, h3, l0, l1, l2, l3;
    split2(acc.x, h0, l0); split2(acc.y, h1, l1);
    split2(acc.z, h2, l2); split2(acc.w, h3, l3);
    size_t base = (size_t)node * KZ + lane * 4;
    *(uint2*)&g_Zh[base] = make_uint2(pk(h0, h1), pk(h2, h3));
    *(uint2*)&g_Zl[base] = make_uint2(pk(l0, l1), pk(l2, l3));

    float dg = g_degf[node];
    float4 xv = X4[(size_t)node * 32 + lane];
    split2(dg * xv.x, h0, l0); split2(dg * xv.y, h1, l1);
    split2(dg * xv.z, h2, l2); split2(dg * xv.w, h3, l3);
    size_t base2 = (size_t)node * KZ + 128 + lane * 4;
    *(uint2*)&g_Zh[base2] = make_uint2(pk(h0, h1), pk(h2, h3));
    *(uint2*)&g_Zl[base2] = make_uint2(pk(l0, l1), pk(l2, l3));
}

// ---------------- per-layer GEMM: Y = leaky(Z @ W^T + deg*b) via bf16-split mma
// BM=128, BN=128 (full N), BK=32. 256 threads = 8 warps (4 m x 2 n),
// warp tile 32x64. C += Zh*Wh + Zh*Wl + Zl*Wh.
__global__ __launch_bounds__(256) void k_gemm(
    const float* __restrict__ W,     // [128][288] fp32
    const float* __restrict__ bvec,  // [128]
    float* __restrict__ oext,
    int osel, int last)
{
    __shared__ __nv_bfloat16 Ah[128 * SK], Al[128 * SK];
    __shared__ __nv_bfloat16 Bh[128 * SK], Bl[128 * SK];
    __shared__ float sb[128];
    int t = threadIdx.x;
    int lane = t & 31, wid = t >> 5;
    int wm = wid >> 1, wn = wid & 1;
    int m0 = blockIdx.x * 128;
    float* out = (osel == 3) ? oext : (osel == 1 ? g_X1 : g_X2);
    if (t < 128) sb[t] = bvec[t];

    float c[2][8][4];
    #pragma unroll
    for (int a = 0; a < 2; a++)
        #pragma unroll
        for (int b = 0; b < 8; b++)
            #pragma unroll
            for (int d = 0; d < 4; d++) c[a][b][d] = 0.f;

    for (int k0 = 0; k0 < KZ; k0 += 32) {
        // stage A (Zh/Zl copy) and B (W fp32 -> split) tiles into smem
        #pragma unroll
        for (int h = 0; h < 2; h++) {
            int fid = t + h * 256;       // 0..511
            int row = fid >> 2, cc = fid & 3;
            int m = m0 + row;
            uint4 vh = make_uint4(0, 0, 0, 0), vl = make_uint4(0, 0, 0, 0);
            if (m < NN) {
                vh = *(const uint4*)&g_Zh[(size_t)m * KZ + k0 + cc * 8];
                vl = *(const uint4*)&g_Zl[(size_t)m * KZ + k0 + cc * 8];
            }
            *(uint4*)&Ah[row * SK + cc * 8] = vh;
            *(uint4*)&Al[row * SK + cc * 8] = vl;

            const float* wp = &W[(size_t)row * KZ + k0 + cc * 8];
            float4 w0 = *(const float4*)wp;
            float4 w1 = *(const float4*)(wp + 4);
            float wv[8] = {w0.x, w0.y, w0.z, w0.w, w1.x, w1.y, w1.z, w1.w};
            __nv_bfloat16 hh[8], ll[8];
            #pragma unroll
            for (int j = 0; j < 8; j++) split2(wv[j], hh[j], ll[j]);
            uint4 bh4 = make_uint4(pk(hh[0], hh[1]), pk(hh[2], hh[3]),
                                   pk(hh[4], hh[5]), pk(hh[6], hh[7]));
            uint4 bl4 = make_uint4(pk(ll[0], ll[1]), pk(ll[2], ll[3]),
                                   pk(ll[4], ll[5]), pk(ll[6], ll[7]));
            *(uint4*)&Bh[row * SK + cc * 8] = bh4;
            *(uint4*)&Bl[row * SK + cc * 8] = bl4;
        }
        __syncthreads();

        #pragma unroll
        for (int kk = 0; kk < 2; kk++) {
            uint32_t ah[2][4], al[2][4];
            #pragma unroll
            for (int mt = 0; mt < 2; mt++) {
                int r = wm * 32 + mt * 16 + (lane & 15);
                int kc = kk * 16 + ((lane >> 4) << 3);
                ldsm4(ah[mt], &Ah[r * SK + kc]);
                ldsm4(al[mt], &Al[r * SK + kc]);
            }
            #pragma unroll
            for (int p = 0; p < 4; p++) {
                int nr = wn * 64 + p * 16 + (lane & 7) + ((lane >> 4) << 3);
                int kc = kk * 16 + (((lane >> 3) & 1) << 3);
                uint32_t bh[4], bl[4];
                ldsm4(bh, &Bh[nr * SK + kc]);
                ldsm4(bl, &Bl[nr * SK + kc]);
                #pragma unroll
                for (int mt = 0; mt < 2; mt++) {
                    mma16816(c[mt][2 * p],     ah[mt], bh);
                    mma16816(c[mt][2 * p + 1], ah[mt], bh + 2);
                    mma16816(c[mt][2 * p],     ah[mt], bl);
                    mma16816(c[mt][2 * p + 1], ah[mt], bl + 2);
                    mma16816(c[mt][2 * p],     al[mt], bh);
                    mma16816(c[mt][2 * p + 1], al[mt], bh + 2);
                }
            }
        }
        __syncthreads();
    }

    // epilogue: y = c + deg*b, leaky (x2 if last)
    #pragma unroll
    for (int mt = 0; mt < 2; mt++) {
        int r0 = m0 + wm * 32 + mt * 16 + (lane >> 2);
        int r1 = r0 + 8;
        float dg0 = (r0 < NN) ? g_degf[r0] : 0.f;
        float dg1 = (r1 < NN) ? g_degf[r1] : 0.f;
        #pragma unroll
        for (int nt = 0; nt < 8; nt++) {
            int col = wn * 64 + nt * 8 + ((lane & 3) << 1);
            float b0 = sb[col], b1 = sb[col + 1];
            if (r0 < NN) {
                float y0 = c[mt][nt][0] + dg0 * b0;
                float y1 = c[mt][nt][1] + dg0 * b1;
                y0 = y0 > 0.f ? y0 : 0.01f * y0;
                y1 = y1 > 0.f ? y1 : 0.01f * y1;
                if (last) {
                    y0 = y0 > 0.f ? y0 : 0.01f * y0;
                    y1 = y1 > 0.f ? y1 : 0.01f * y1;
                }
                *(float2*)&out[(size_t)r0 * HD + col] = make_float2(y0, y1);
            }
            if (r1 < NN) {
                float y2 = c[mt][nt][2] + dg1 * b0;
                float y3 = c[mt][nt][3] + dg1 * b1;
                y2 = y2 > 0.f ? y2 : 0.01f * y2;
                y3 = y3 > 0.f ? y3 : 0.01f * y3;
                if (last) {
                    y2 = y2 > 0.f ? y2 : 0.01f * y2;
                    y3 = y3 > 0.f ? y3 : 0.01f * y3;
                }
                *(float2*)&out[(size_t)r1 * HD + col] = make_float2(y2, y3);
            }
        }
    }
}

// ---------------- launch ----------------
extern "C" void kernel_launch(void* const* d_in, const int* in_sizes, int n_in,
                              void* d_out, int out_size) {
    const float* x  = nullptr;
    const void*  ei = nullptr;
    const float* ea = nullptr;
    const float* Wm = nullptr;
    const float* bm = nullptr;
    for (int i = 0; i < n_in; i++) {
        switch (in_sizes[i]) {
            case 12800000: x  = (const float*)d_in[i]; break;
            case 1600000:  ei = d_in[i];               break;
            case 25600000: ea = (const float*)d_in[i]; break;
            case 110592:   Wm = (const float*)d_in[i]; break;
            case 384:      bm = (const float*)d_in[i]; break;
            default: break;
        }
    }
    float* out = (float*)d_out;

    const int nblk = (NN + 1023) / 1024;   // 98
    k_detect<<<1, 1>>>((const int*)ei);
    k_zero_deg<<<(NN + 255) / 256, 256>>>();
    k_hist<<<(NE + 255) / 256, 256>>>(ei);
    k_scan1<<<nblk, 1024>>>();
    k_scan2<<<1, 1>>>(nblk);
    k_scan3<<<(NN + 255) / 256, 256>>>();
    k_fill<<<(NE + 255) / 256, 256>>>(ei);
    k_pre<<<(NN * 32 + 255) / 256, 256>>>(ea);

    const int gemm_blocks = (NN + 127) / 128;   // 782
    // layer 0: in = x,    out = g_X1
    k_spmm<<<(NN * 32 + 255) / 256, 256>>>(x, 0);
    k_gemm<<<gemm_blocks, 256>>>(Wm + 0 * (size_t)HD * KZ, bm + 0 * HD, out, 1, 0);
    // layer 1: in = g_X1, out = g_X2
    k_spmm<<<(NN * 32 + 255) / 256, 256>>>(nullptr, 1);
    k_gemm<<<gemm_blocks, 256>>>(Wm + 1 * (size_t)HD * KZ, bm + 1 * HD, out, 2, 0);
    // layer 2: in = g_X2, out = d_out (double leaky: activate_last)
    k_spmm<<<(NN * 32 + 255) / 256, 256>>>(nullptr, 2);
    k_gemm<<<gemm_blocks, 256>>>(Wm + 2 * (size_t)HD * KZ, bm + 2 * HD, out, 3, 1);
}